// round 14
// baseline (speedup 1.0000x reference)
#include <cuda_runtime.h>
#include <cuda_bf16.h>
#include <math_constants.h>

// Problem dims (fixed by the reference)
#define BB 4
#define TT 2048
#define CC 1024
#define HH 16
#define DD 64
#define BT (BB*TT)      // 8192 rows
#define F3 (3*CC)       // 3072 qkv features

// Scratch (allocation-free rule: __device__ globals)
__device__ float g_qkv[BT * F3];   // 100.7 MB
__device__ float g_att[BT * CC];   // 33.6 MB

// ---------------------------------------------------------------------------
// bf16x3 helpers: x = hi + lo (each bf16); D += hi*hi + hi*lo + lo*hi
// ---------------------------------------------------------------------------
__device__ __forceinline__ unsigned pack2(float a, float b) {
    __nv_bfloat162 t = __floats2bfloat162_rn(a, b);  // low 16 = a
    return *reinterpret_cast<unsigned*>(&t);
}
__device__ __forceinline__ void split2(float a, float b, unsigned& hi, unsigned& lo) {
    float ah = __bfloat162float(__float2bfloat16(a));
    float bh = __bfloat162float(__float2bfloat16(b));
    hi = pack2(ah, bh);
    lo = pack2(a - ah, b - bh);
}

__device__ __forceinline__ void mma_bf16(float c[4], const unsigned a[4],
                                         unsigned b0, unsigned b1) {
    asm volatile(
        "mma.sync.aligned.m16n8k16.row.col.f32.bf16.bf16.f32 "
        "{%0,%1,%2,%3},{%4,%5,%6,%7},{%8,%9},{%0,%1,%2,%3};"
        : "+f"(c[0]), "+f"(c[1]), "+f"(c[2]), "+f"(c[3])
        : "r"(a[0]), "r"(a[1]), "r"(a[2]), "r"(a[3]), "r"(b0), "r"(b1));
}
#define MMA_BF16 mma_bf16

// ---------------------------------------------------------------------------
// Tensor-core GEMM (NT): C[m][n] = sum_k A[m][k] * W[n][k]
// CTA tile 128x256, BK=16, 256 threads = 8 warps (2m x 4n), warp tile 64x64.
// (m=4, n=8 MMA tiles per warp: LDS words/MMA = 0.67 vs 1.0 at 64x32.)
// bf16 hi/lo pre-split at staging; register-staged LDG prefetch.
// Smem word pitch 20 (16 k -> 8 words + 2 pad): (20*lr+lc)%32 all distinct.
// ---------------------------------------------------------------------------
#define GW 20   // 32-bit words per smem row
#define GEMM_SMEM ((128 + 128 + 256 + 256) * GW * 4)   // 61440 B

__global__ void __launch_bounds__(256) gemm_nt_tc_kernel(
    const float* __restrict__ A, const float* __restrict__ W,
    float* __restrict__ C, int M, int N, int K)
{
    extern __shared__ unsigned gsm[];
    unsigned* Ah = gsm;                    // [128][GW]
    unsigned* Al = Ah + 128 * GW;
    unsigned* Bh = Al + 128 * GW;          // [256][GW]
    unsigned* Bl = Bh + 256 * GW;

    const int tid    = threadIdx.x;
    const int lane   = tid & 31;
    const int warp   = tid >> 5;
    const int warp_m = warp >> 2;          // 0..1 -> 64-row slab
    const int warp_n = warp & 3;           // 0..3 -> 64-col slab
    const int lr     = lane >> 2;          // 0..7
    const int lc     = lane & 3;           // 0..3
    const int m0     = blockIdx.y * 128;
    const int n0     = blockIdx.x * 256;

    const int ldr = tid >> 2;              // 0..63 loader row
    const int ldk = (tid & 3) << 2;        // k sub-offset (floats)

    float acc[4][8][4];
    #pragma unroll
    for (int i = 0; i < 4; i++)
        #pragma unroll
        for (int j = 0; j < 8; j++)
            #pragma unroll
            for (int f = 0; f < 4; f++) acc[i][j][f] = 0.f;

    float4 rA[2], rB[4];
    auto ldg_tile = [&](int k0) {
        #pragma unroll
        for (int it = 0; it < 2; it++)
            rA[it] = *(const float4*)(A + (size_t)(m0 + ldr + it * 64) * K + k0 + ldk);
        #pragma unroll
        for (int it = 0; it < 4; it++)
            rB[it] = *(const float4*)(W + (size_t)(n0 + ldr + it * 64) * K + k0 + ldk);
    };
    auto sts_split = [&]() {
        #pragma unroll
        for (int it = 0; it < 2; it++) {
            int wb = (ldr + it * 64) * GW + (ldk >> 1);
            unsigned hi, lo;
            split2(rA[it].x, rA[it].y, hi, lo);
            Ah[wb] = hi;     Al[wb] = lo;
            split2(rA[it].z, rA[it].w, hi, lo);
            Ah[wb + 1] = hi; Al[wb + 1] = lo;
        }
        #pragma unroll
        for (int it = 0; it < 4; it++) {
            int wb = (ldr + it * 64) * GW + (ldk >> 1);
            unsigned hi, lo;
            split2(rB[it].x, rB[it].y, hi, lo);
            Bh[wb] = hi;     Bl[wb] = lo;
            split2(rB[it].z, rB[it].w, hi, lo);
            Bh[wb + 1] = hi; Bl[wb + 1] = lo;
        }
    };

    const int KT = K >> 4;
    ldg_tile(0);

    for (int kt = 0; kt < KT; kt++) {
        sts_split();
        __syncthreads();
        if (kt + 1 < KT) ldg_tile((kt + 1) << 4);   // overlap with compute

        unsigned ah[4][4], al[4][4];
        #pragma unroll
        for (int mt = 0; mt < 4; mt++) {
            int ab = (warp_m * 64 + mt * 16 + lr) * GW + lc;
            ah[mt][0] = Ah[ab];
            ah[mt][1] = Ah[ab + 8 * GW];
            ah[mt][2] = Ah[ab + 4];
            ah[mt][3] = Ah[ab + 8 * GW + 4];
            al[mt][0] = Al[ab];
            al[mt][1] = Al[ab + 8 * GW];
            al[mt][2] = Al[ab + 4];
            al[mt][3] = Al[ab + 8 * GW + 4];
        }
        #pragma unroll
        for (int nt = 0; nt < 8; nt++) {
            int bb = (warp_n * 64 + nt * 8 + lr) * GW + lc;
            unsigned bh0 = Bh[bb], bh1 = Bh[bb + 4];
            unsigned bl0 = Bl[bb], bl1 = Bl[bb + 4];
            #pragma unroll
            for (int mt = 0; mt < 4; mt++) {
                MMA_BF16(acc[mt][nt], ah[mt], bh0, bh1);
                MMA_BF16(acc[mt][nt], ah[mt], bl0, bl1);
                MMA_BF16(acc[mt][nt], al[mt], bh0, bh1);
            }
        }
        __syncthreads();
    }

    #pragma unroll
    for (int mt = 0; mt < 4; mt++) {
        #pragma unroll
        for (int nt = 0; nt < 8; nt++) {
            int r  = m0 + warp_m * 64 + mt * 16 + lr;
            int cc = n0 + warp_n * 64 + nt * 8 + 2 * lc;
            *(float2*)(C + (size_t)r * N + cc)       = make_float2(acc[mt][nt][0], acc[mt][nt][1]);
            *(float2*)(C + (size_t)(r + 8) * N + cc) = make_float2(acc[mt][nt][2], acc[mt][nt][3]);
        }
    }
}

// ---------------------------------------------------------------------------
// Flash attention (causal), bf16x3 TC — unchanged from the R11 passing kernel.
// Block = 128 q-rows; 8 warps, warp-local softmax, register-resident P.
// ---------------------------------------------------------------------------
#define AW 36                     // words per 64-d row (32 data + 4 pad)
#define KV_SZ (64 * AW)           // words per K/V operand tile
#define Q_SZ  (128 * AW)          // words per Q operand (128 rows)
#define ATT_SMEM ((2 * Q_SZ + 4 * KV_SZ) * 4)   // 73728 B

__global__ void __launch_bounds__(256, 2) attn_kernel(
    const float* __restrict__ qkv, float* __restrict__ att)
{
    extern __shared__ unsigned smw[];
    unsigned* Qh  = smw;               // [128][AW] packed d-pairs
    unsigned* Ql  = Qh + Q_SZ;
    unsigned* Kh  = Ql + Q_SZ;         // [key][d-pairs]
    unsigned* Kl  = Kh + KV_SZ;
    unsigned* Vth = Kl + KV_SZ;        // [d][key-pairs]
    unsigned* Vtl = Vth + KV_SZ;
    __nv_bfloat16* Vthb = (__nv_bfloat16*)Vth;
    __nv_bfloat16* Vtlb = (__nv_bfloat16*)Vtl;

    const int tid  = threadIdx.x;
    const int lane = tid & 31;
    const int warp = tid >> 5;         // 0..7 -> 16 q-rows each
    const int g    = lane >> 2;        // 0..7 row-in-group
    const int tig  = lane & 3;         // 0..3
    const int bh   = blockIdx.y;
    const int b    = bh >> 4;
    const int h    = bh & 15;
    const int q0   = blockIdx.x * 128;

    const int qrow = q0 + warp * 16 + g;   // global q row (and +8)

    const float* qbase = qkv + (size_t)(b*TT + q0) * F3 + h*DD;
    const float* kbase = qkv + (size_t)(b*TT) * F3 + CC   + h*DD;
    const float* vbase = qkv + (size_t)(b*TT) * F3 + 2*CC + h*DD;

    // Stage Q (scaled by 1/8), split hi/lo, packed d-pairs
    {
        const float scale = 0.125f;
        #pragma unroll
        for (int it = 0; it < 8; it++) {
            int fi = tid + it * 256;
            int r  = fi >> 4;
            int d0 = (fi & 15) << 2;
            float4 v = *(const float4*)(qbase + (size_t)r * F3 + d0);
            int wb = r * AW + (d0 >> 1);
            unsigned hi, lo;
            split2(v.x * scale, v.y * scale, hi, lo);
            Qh[wb] = hi;     Ql[wb] = lo;
            split2(v.z * scale, v.w * scale, hi, lo);
            Qh[wb + 1] = hi; Ql[wb + 1] = lo;
        }
    }

    float m0s = -CUDART_INF_F, m1s = -CUDART_INF_F;
    float l0s = 0.f, l1s = 0.f;
    float oacc[8][4];
    #pragma unroll
    for (int nt = 0; nt < 8; nt++)
        #pragma unroll
        for (int f = 0; f < 4; f++) oacc[nt][f] = 0.f;

    const int nkt = (q0 >> 6) + 2;
    for (int kt = 0; kt < nkt; kt++) {
        const int k0 = kt * 64;

        __syncthreads();   // prior tile consumed (and Q staged on iter 0)
        #pragma unroll
        for (int it = 0; it < 4; it++) {
            int fi = tid + it * 256;
            int r  = fi >> 4;             // key
            int d0 = (fi & 15) << 2;
            float4 kv = *(const float4*)(kbase + (size_t)(k0 + r) * F3 + d0);
            int wb = r * AW + (d0 >> 1);
            unsigned hi, lo;
            split2(kv.x, kv.y, hi, lo);
            Kh[wb] = hi;     Kl[wb] = lo;
            split2(kv.z, kv.w, hi, lo);
            Kh[wb + 1] = hi; Kl[wb + 1] = lo;

            float4 vv4 = *(const float4*)(vbase + (size_t)(k0 + r) * F3 + d0);
            float vv[4] = { vv4.x, vv4.y, vv4.z, vv4.w };
            #pragma unroll
            for (int j = 0; j < 4; j++) {
                __nv_bfloat16 vh = __float2bfloat16(vv[j]);
                Vthb[(d0 + j) * (2*AW) + r] = vh;
                Vtlb[(d0 + j) * (2*AW) + r] =
                    __float2bfloat16(vv[j] - __bfloat162float(vh));
            }
        }
        __syncthreads();

        // Warp-uniform causal tile skip
        if (k0 > q0 + warp * 16 + 15) continue;

        // S = Q K^T : 16 q-rows x 64 keys
        float sacc[8][4];
        #pragma unroll
        for (int nt = 0; nt < 8; nt++)
            #pragma unroll
            for (int f = 0; f < 4; f++) sacc[nt][f] = 0.f;

        const int qb = (warp * 16 + g) * AW;
        #pragma unroll
        for (int kk = 0; kk < 4; kk++) {
            int ab = qb + kk * 8 + tig;
            unsigned ah[4], al[4];
            ah[0] = Qh[ab];          ah[1] = Qh[ab + 8 * AW];
            ah[2] = Qh[ab + 4];      ah[3] = Qh[ab + 8 * AW + 4];
            al[0] = Ql[ab];          al[1] = Ql[ab + 8 * AW];
            al[2] = Ql[ab + 4];      al[3] = Ql[ab + 8 * AW + 4];
            #pragma unroll
            for (int nt = 0; nt < 8; nt++) {
                int bb = (nt * 8 + g) * AW + kk * 8 + tig;
                unsigned bh0 = Kh[bb], bh1 = Kh[bb + 4];
                unsigned bl0 = Kl[bb], bl1 = Kl[bb + 4];
                MMA_BF16(sacc[nt], ah, bh0, bh1);
                MMA_BF16(sacc[nt], ah, bl0, bl1);
                MMA_BF16(sacc[nt], al, bh0, bh1);
            }
        }

        // Causal mask where tile overlaps the warp's diagonal
        if (k0 + 63 > q0 + warp * 16) {
            #pragma unroll
            for (int nt = 0; nt < 8; nt++) {
                int key = k0 + nt * 8 + 2 * tig;
                if (key     > qrow)     sacc[nt][0] = -CUDART_INF_F;
                if (key + 1 > qrow)     sacc[nt][1] = -CUDART_INF_F;
                if (key     > qrow + 8) sacc[nt][2] = -CUDART_INF_F;
                if (key + 1 > qrow + 8) sacc[nt][3] = -CUDART_INF_F;
            }
        }

        // Warp-local online softmax (rows live in quads: shfl xor 1,2)
        float tm0 = -CUDART_INF_F, tm1 = -CUDART_INF_F;
        #pragma unroll
        for (int nt = 0; nt < 8; nt++) {
            tm0 = fmaxf(tm0, fmaxf(sacc[nt][0], sacc[nt][1]));
            tm1 = fmaxf(tm1, fmaxf(sacc[nt][2], sacc[nt][3]));
        }
        tm0 = fmaxf(tm0, __shfl_xor_sync(0xffffffffu, tm0, 1));
        tm0 = fmaxf(tm0, __shfl_xor_sync(0xffffffffu, tm0, 2));
        tm1 = fmaxf(tm1, __shfl_xor_sync(0xffffffffu, tm1, 1));
        tm1 = fmaxf(tm1, __shfl_xor_sync(0xffffffffu, tm1, 2));
        float mn0 = fmaxf(m0s, tm0), mn1 = fmaxf(m1s, tm1);
        float sc0 = __expf(m0s - mn0), sc1 = __expf(m1s - mn1);
        m0s = mn0; m1s = mn1;

        float rs0 = 0.f, rs1 = 0.f;
        #pragma unroll
        for (int nt = 0; nt < 8; nt++) {
            sacc[nt][0] = __expf(sacc[nt][0] - mn0);
            sacc[nt][1] = __expf(sacc[nt][1] - mn0);
            sacc[nt][2] = __expf(sacc[nt][2] - mn1);
            sacc[nt][3] = __expf(sacc[nt][3] - mn1);
            rs0 += sacc[nt][0] + sacc[nt][1];
            rs1 += sacc[nt][2] + sacc[nt][3];
        }
        rs0 += __shfl_xor_sync(0xffffffffu, rs0, 1);
        rs0 += __shfl_xor_sync(0xffffffffu, rs0, 2);
        rs1 += __shfl_xor_sync(0xffffffffu, rs1, 1);
        rs1 += __shfl_xor_sync(0xffffffffu, rs1, 2);
        l0s = l0s * sc0 + rs0;
        l1s = l1s * sc1 + rs1;

        #pragma unroll
        for (int nt = 0; nt < 8; nt++) {
            oacc[nt][0] *= sc0; oacc[nt][1] *= sc0;
            oacc[nt][2] *= sc1; oacc[nt][3] *= sc1;
        }

        // O += P V : P straight from registers (S C-frag == PV A-frag layout)
        #pragma unroll
        for (int kk = 0; kk < 4; kk++) {
            unsigned ph[4], pl[4];
            split2(sacc[2*kk][0],   sacc[2*kk][1],   ph[0], pl[0]);
            split2(sacc[2*kk][2],   sacc[2*kk][3],   ph[1], pl[1]);
            split2(sacc[2*kk+1][0], sacc[2*kk+1][1], ph[2], pl[2]);
            split2(sacc[2*kk+1][2], sacc[2*kk+1][3], ph[3], pl[3]);
            #pragma unroll
            for (int nt = 0; nt < 8; nt++) {
                int bb = (nt * 8 + g) * AW + kk * 8 + tig;
                unsigned vh0 = Vth[bb], vh1 = Vth[bb + 4];
                unsigned vl0 = Vtl[bb], vl1 = Vtl[bb + 4];
                MMA_BF16(oacc[nt], ph, vh0, vh1);
                MMA_BF16(oacc[nt], ph, vl0, vl1);
                MMA_BF16(oacc[nt], pl, vh0, vh1);
            }
        }
    }

    // Epilogue: normalize, write [B,T,C] head-interleaved
    float inv0 = 1.f / l0s, inv1 = 1.f / l1s;
    #pragma unroll
    for (int nt = 0; nt < 8; nt++) {
        int c = h*DD + nt * 8 + 2 * tig;
        float* o0 = att + (size_t)(b*TT + qrow) * CC + c;
        float* o1 = att + (size_t)(b*TT + qrow + 8) * CC + c;
        *(float2*)o0 = make_float2(oacc[nt][0] * inv0, oacc[nt][1] * inv0);
        *(float2*)o1 = make_float2(oacc[nt][2] * inv1, oacc[nt][3] * inv1);
    }
}

// ---------------------------------------------------------------------------
// Launch: QKV GEMM -> TC flash attention -> proj GEMM
// ---------------------------------------------------------------------------
extern "C" void kernel_launch(void* const* d_in, const int* in_sizes, int n_in,
                              void* d_out, int out_size)
{
    (void)in_sizes; (void)n_in; (void)out_size;
    const float* x      = (const float*)d_in[0];
    const float* w_qkv  = (const float*)d_in[1];
    const float* w_proj = (const float*)d_in[2];
    float* out = (float*)d_out;

    float* qkv = nullptr;
    float* attb = nullptr;
    cudaGetSymbolAddress((void**)&qkv,  g_qkv);
    cudaGetSymbolAddress((void**)&attb, g_att);

    cudaFuncSetAttribute(gemm_nt_tc_kernel,
                         cudaFuncAttributeMaxDynamicSharedMemorySize, GEMM_SMEM);
    cudaFuncSetAttribute(attn_kernel,
                         cudaFuncAttributeMaxDynamicSharedMemorySize, ATT_SMEM);

    dim3 g1(F3 / 256, BT / 128);        // (12, 64)
    gemm_nt_tc_kernel<<<g1, 256, GEMM_SMEM>>>(x, w_qkv, qkv, BT, F3, CC);

    dim3 g2(TT / 128, BB * HH);         // (16, 64)
    attn_kernel<<<g2, 256, ATT_SMEM>>>(qkv, attb);

    dim3 g3(CC / 256, BT / 128);        // (4, 64)
    gemm_nt_tc_kernel<<<g3, 256, GEMM_SMEM>>>(attb, w_proj, out, BT, CC, CC);
}